// round 14
// baseline (speedup 1.0000x reference)
#include <cuda_runtime.h>
#include <cuda_fp16.h>
#include <math.h>

#define BATCH 128
#define NCAP  4608
#define JDIM  8
#define CDIM  10
#define LDIM  16
#define CL    160
#define BSPL  4               // b-splits (32 b each)
#define NSPL  72              // n-splits
#define FN    (NCAP/NSPL)     // 64 n per block
#define THR   320
#define WST   2560            // bytes per W stage (160 rows * 16B)

// smem byte offsets (dynamic smem)
#define SM_X   0                     // 64n*32b*8j fp16 = 32768
#define SM_W   32768                 // 8 stages * 2560 = 20480
#define SM_V   53248                 // 10c*32b*16l fp32 = 20480
#define SM_SE  73728                 // 2n * 10c * 32b fp32 = 2560
#define SM_TOT 76288

// Scratch (static device globals; no dynamic allocation allowed)
__device__ __align__(16) __half g_Wh[(size_t)NCAP * CL * JDIM];  // [n][cl][8j] fp16
__device__ __align__(16) float g_s0[BATCH * CDIM * LDIM];
__device__ __align__(16) float g_s1[BATCH * CDIM * LDIM];
__device__ __align__(16) float g_s2[BATCH * CDIM * LDIM];

// ---- helpers ----------------------------------------------------------------
__device__ __forceinline__ unsigned int cvt2h(float lo, float hi) {
    unsigned int h;
    asm("cvt.rn.f16x2.f32 %0, %1, %2;" : "=r"(h) : "f"(hi), "f"(lo));
    return h;
}
__device__ __forceinline__ float squash_factor(float n2) {
    return n2 / (1.0f + n2) / (sqrtf(n2) + 1e-7f);
}
// Fast exp on fma/alu pipes. |x| small, rel err ~4e-5.
__device__ __forceinline__ float fexp(float x) {
    float t = x * 1.4426950408889634f;
    float z = t + 12582912.0f;
    int   ki = __float_as_int(z);
    float k = z - 12582912.0f;
    float f = t - k;
    float p = 0.0096181291f;
    p = fmaf(p, f, 0.0555041087f);
    p = fmaf(p, f, 0.2402265070f);
    p = fmaf(p, f, 0.6931471806f);
    p = fmaf(p, f, 1.0f);
    return __int_as_float(__float_as_int(p) + (ki << 23));
}
__device__ __forceinline__ void cpasync16(unsigned int sdst, const void* gsrc) {
    asm volatile("cp.async.cg.shared.global [%0], [%1], 16;" :: "r"(sdst), "l"(gsrc) : "memory");
}
__device__ __forceinline__ void cpasync_commit() {
    asm volatile("cp.async.commit_group;" ::: "memory");
}
__device__ __forceinline__ void cpasync_wait4() {
    asm volatile("cp.async.wait_group 4;" ::: "memory");
}
__device__ __forceinline__ unsigned int smem_u32(const void* p) {
    return (unsigned int)__cvta_generic_to_shared(p);
}
__device__ __forceinline__ void ldsm_x2(unsigned int& r0, unsigned int& r1, unsigned int a) {
    asm volatile("ldmatrix.sync.aligned.m8n8.x2.shared.b16 {%0,%1}, [%2];"
                 : "=r"(r0), "=r"(r1) : "r"(a));
}
__device__ __forceinline__ void ldsm_x4(unsigned int& r0, unsigned int& r1,
                                        unsigned int& r2, unsigned int& r3, unsigned int a) {
    asm volatile("ldmatrix.sync.aligned.m8n8.x4.shared.b16 {%0,%1,%2,%3}, [%4];"
                 : "=r"(r0), "=r"(r1), "=r"(r2), "=r"(r3) : "r"(a));
}
__device__ __forceinline__ void mma_16n8k8(float* c, unsigned int a0, unsigned int a1,
                                           unsigned int b0) {
    asm volatile("mma.sync.aligned.m16n8k8.row.col.f32.f16.f16.f32 "
                 "{%0,%1,%2,%3}, {%4,%5}, {%6}, {%7,%7,%7,%7};"
                 : "=f"(c[0]), "=f"(c[1]), "=f"(c[2]), "=f"(c[3])
                 : "r"(a0), "r"(a1), "r"(b0), "f"(0.0f));
}

// ---------------------------------------------------------------------------
// W prep: W[n][j][cl] fp32 -> g_Wh[n][cl][8j] fp16; zero s buffers.
// ---------------------------------------------------------------------------
__global__ void transpose_W_kernel(const float* __restrict__ W) {
    int n = blockIdx.x;
    int cl = threadIdx.x;     // 0..159
    if (n < 128) {
        int z = n * CL + cl;
        g_s0[z] = 0.0f; g_s1[z] = 0.0f; g_s2[z] = 0.0f;
    }
    const float* Wn = W + (size_t)n * JDIM * CL;
    unsigned int h[4];
#pragma unroll
    for (int p = 0; p < 4; ++p)
        h[p] = cvt2h(Wn[(2 * p) * CL + cl], Wn[(2 * p + 1) * CL + cl]);
    *reinterpret_cast<uint4*>(g_Wh + ((size_t)n * CL + cl) * JDIM) =
        make_uint4(h[0], h[1], h[2], h[3]);
}

// ---------------------------------------------------------------------------
// Fused routing pass, G=2 n per barrier group; e-values published directly
// (exp folded into the exchange) so softmax needs ONE barrier per group.
// Block: 32 b x 64 n. 320 thr / 10 warps; warp w: mt=w&1, cA=w>>1, cB=cA+5.
// MODE 0: s0 += u. MODE 1: v=squash(s0/C+bias); s1 += coef*u.
// MODE 2: v=squash(s0/C+bias)+squash(s1+bias);  s2 += coef*u.
// ---------------------------------------------------------------------------
template <int MODE>
__global__ __launch_bounds__(THR, 2) void fused_pass(const float* __restrict__ x,
                                                     const float* __restrict__ biases) {
    extern __shared__ __align__(16) char smem[];
    __half* sX = (__half*)(smem + SM_X);
    float*  sV = (float*)(smem + SM_V);
    float*  sE = (float*)(smem + SM_SE);     // [j][c][b]

    const int tid  = threadIdx.x;
    const int lane = tid & 31;
    const int w    = tid >> 5;          // 0..9
    const int mt   = w & 1;
    const int cA   = w >> 1;            // 0..4
    const int cB   = cA + 5;
    const int Bb   = blockIdx.x * 32;
    const int nbeg = blockIdx.y * FN;

    // ---- prologue: stage x chunk (32 KB fp16) ----
    for (int k = tid; k < 32 * FN * 2; k += THR) {
        int b   = k >> 7;
        int rem = k & 127;
        int nl  = rem >> 1;
        int jh  = (rem & 1) * 4;
        float4 xv = *(const float4*)(x + ((size_t)(Bb + b) * NCAP + nbeg + nl) * JDIM + jh);
        *(uint2*)&sX[(nl * 32 + b) * JDIM + jh] =
            make_uint2(cvt2h(xv.x, xv.y), cvt2h(xv.z, xv.w));
    }
    // ---- prologue: v per (b,c) ----
    if (MODE >= 1) {
        int b = tid & 31, c = tid >> 5;
        const float4* s0p = (const float4*)(g_s0 + ((size_t)(Bb + b) * CDIM + c) * LDIM);
        const float4* bp  = (const float4*)(biases + c * LDIM);
        float v[16]; float n20 = 0.0f;
#pragma unroll
        for (int q = 0; q < 4; ++q) {
            float4 sv = s0p[q], bv = bp[q];
            v[q*4+0] = 0.1f*sv.x + bv.x; v[q*4+1] = 0.1f*sv.y + bv.y;
            v[q*4+2] = 0.1f*sv.z + bv.z; v[q*4+3] = 0.1f*sv.w + bv.w;
            n20 += v[q*4+0]*v[q*4+0] + v[q*4+1]*v[q*4+1]
                 + v[q*4+2]*v[q*4+2] + v[q*4+3]*v[q*4+3];
        }
        float f0 = squash_factor(n20);
        if (MODE == 1) {
#pragma unroll
            for (int l = 0; l < 16; ++l) v[l] *= f0;
        } else {
            const float4* s1p = (const float4*)(g_s1 + ((size_t)(Bb + b) * CDIM + c) * LDIM);
            float wv[16]; float n21 = 0.0f;
#pragma unroll
            for (int q = 0; q < 4; ++q) {
                float4 sv = s1p[q], bv = bp[q];
                wv[q*4+0] = sv.x + bv.x; wv[q*4+1] = sv.y + bv.y;
                wv[q*4+2] = sv.z + bv.z; wv[q*4+3] = sv.w + bv.w;
                n21 += wv[q*4+0]*wv[q*4+0] + wv[q*4+1]*wv[q*4+1]
                     + wv[q*4+2]*wv[q*4+2] + wv[q*4+3]*wv[q*4+3];
            }
            float f1 = squash_factor(n21);
#pragma unroll
            for (int l = 0; l < 16; ++l) v[l] = f0 * v[l] + f1 * wv[l];
        }
        float4* dv = (float4*)(sV + (c * 32 + b) * 16);
#pragma unroll
        for (int q = 0; q < 4; ++q)
            dv[q] = make_float4(v[q*4+0], v[q*4+1], v[q*4+2], v[q*4+3]);
    }
    __syncthreads();

    const int blq  = mt * 16 + (lane >> 2);
    const int lodd = (lane & 3) * 2;
    float Vl[4][2], Vh[4][2];
    if (MODE >= 1) {
#pragma unroll
        for (int t = 0; t < 4; ++t) {
            int ct = (t < 2) ? cA : cB;
            int l0 = (t & 1) * 8 + lodd;
            Vl[t][0] = sV[(ct * 32 + blq) * 16 + l0];
            Vl[t][1] = sV[(ct * 32 + blq) * 16 + l0 + 1];
            Vh[t][0] = sV[(ct * 32 + blq + 8) * 16 + l0];
            Vh[t][1] = sV[(ct * 32 + blq + 8) * 16 + l0 + 1];
        }
    }

    // ---- W cp.async ring: 8 stages of 1 n each ----
    const unsigned int swb = smem_u32(smem + SM_W);
    auto fillW = [&](int stage, int i) {
        if (tid < CL && i < FN)
            cpasync16(swb + stage * WST + tid * 16,
                      g_Wh + ((size_t)(nbeg + i) * CL + tid) * JDIM);
    };
#pragma unroll
    for (int i = 0; i < 6; ++i) { fillW(i, i); cpasync_commit(); }

    const unsigned int aaddr0 = smem_u32(sX) + (mt * 16 + (lane & 15)) * JDIM * 2;
    const int clrow = ((lane < 16) ? cA * 16 + lane : cB * 16 + lane - 16);
    const unsigned int baddr0 = swb + clrow * 16;

    float sacc[4][4];
#pragma unroll
    for (int t = 0; t < 4; ++t)
#pragma unroll
        for (int k = 0; k < 4; ++k) sacc[t][k] = 0.0f;

    for (int g = 0; g < FN / 2; ++g) {
        const int i0 = g * 2;
        cpasync_wait4();
        __syncthreads();                          // bar A: stages i0, i0+1 ready
        fillW((i0 + 6) & 7, i0 + 6); cpasync_commit();
        fillW((i0 + 7) & 7, i0 + 7); cpasync_commit();

        float c4[2][4][4];
#pragma unroll
        for (int j = 0; j < 2; ++j) {
            unsigned int a0, a1, bf0, bf1, bf2, bf3;
            ldsm_x2(a0, a1, aaddr0 + (i0 + j) * 512);
            ldsm_x4(bf0, bf1, bf2, bf3, baddr0 + ((i0 + j) & 7) * WST);
            mma_16n8k8(c4[j][0], a0, a1, bf0);
            mma_16n8k8(c4[j][1], a0, a1, bf1);
            mma_16n8k8(c4[j][2], a0, a1, bf2);
            mma_16n8k8(c4[j][3], a0, a1, bf3);
        }

        if (MODE == 0) {
#pragma unroll
            for (int j = 0; j < 2; ++j)
#pragma unroll
                for (int t = 0; t < 4; ++t)
#pragma unroll
                    for (int k = 0; k < 4; ++k) sacc[t][k] += c4[j][t][k];
        } else {
#pragma unroll
            for (int j = 0; j < 2; ++j) {
                float bla = c4[j][0][0]*Vl[0][0] + c4[j][0][1]*Vl[0][1]
                          + c4[j][1][0]*Vl[1][0] + c4[j][1][1]*Vl[1][1];
                float bha = c4[j][0][2]*Vh[0][0] + c4[j][0][3]*Vh[0][1]
                          + c4[j][1][2]*Vh[1][0] + c4[j][1][3]*Vh[1][1];
                float blb = c4[j][2][0]*Vl[2][0] + c4[j][2][1]*Vl[2][1]
                          + c4[j][3][0]*Vl[3][0] + c4[j][3][1]*Vl[3][1];
                float bhb = c4[j][2][2]*Vh[2][0] + c4[j][2][3]*Vh[2][1]
                          + c4[j][3][2]*Vh[3][0] + c4[j][3][3]*Vh[3][1];
#pragma unroll
                for (int d = 1; d <= 2; d <<= 1) {
                    bla += __shfl_xor_sync(0xFFFFFFFFu, bla, d);
                    bha += __shfl_xor_sync(0xFFFFFFFFu, bha, d);
                    blb += __shfl_xor_sync(0xFFFFFFFFu, blb, d);
                    bhb += __shfl_xor_sync(0xFFFFFFFFu, bhb, d);
                }
                // distributed exchange: publish e = exp(bd) directly
                int sel = lane & 3;
                float bv = (sel == 0) ? bla : (sel == 1) ? bha : (sel == 2) ? blb : bhb;
                int bb = mt * 16 + (lane >> 2) + ((sel & 1) ? 8 : 0);
                int cc = (sel & 2) ? cB : cA;
                sE[(j * CDIM + cc) * 32 + bb] = fexp(bv);
            }
            __syncthreads();                      // bar B: all e-values ready
#pragma unroll
            for (int j = 0; j < 2; ++j) {
                const float* ej = sE + j * CDIM * 32;
                float Sl = 0.0f, Sh = 0.0f;
#pragma unroll
                for (int cc = 0; cc < CDIM; ++cc) {
                    Sl += ej[cc * 32 + blq];
                    Sh += ej[cc * 32 + blq + 8];
                }
                float il = __fdividef(1.0f, Sl);
                float ih = __fdividef(1.0f, Sh);
                float cla = ej[cA * 32 + blq] * il;
                float cha = ej[cA * 32 + blq + 8] * ih;
                float clb = ej[cB * 32 + blq] * il;
                float chb = ej[cB * 32 + blq + 8] * ih;
#pragma unroll
                for (int t = 0; t < 2; ++t) {
                    sacc[t][0] += cla * c4[j][t][0];
                    sacc[t][1] += cla * c4[j][t][1];
                    sacc[t][2] += cha * c4[j][t][2];
                    sacc[t][3] += cha * c4[j][t][3];
                }
#pragma unroll
                for (int t = 2; t < 4; ++t) {
                    sacc[t][0] += clb * c4[j][t][0];
                    sacc[t][1] += clb * c4[j][t][1];
                    sacc[t][2] += chb * c4[j][t][2];
                    sacc[t][3] += chb * c4[j][t][3];
                }
            }
        }
    }

    // flush partials
    float* dst = (MODE == 0) ? g_s0 : (MODE == 1) ? g_s1 : g_s2;
    const int bg = Bb + blq;
#pragma unroll
    for (int t = 0; t < 4; ++t) {
        int ct = (t < 2) ? cA : cB;
        int l0 = (t & 1) * 8 + lodd;
        atomicAdd(&dst[((size_t)bg * CDIM + ct) * LDIM + l0],     sacc[t][0]);
        atomicAdd(&dst[((size_t)bg * CDIM + ct) * LDIM + l0 + 1], sacc[t][1]);
        atomicAdd(&dst[((size_t)(bg + 8) * CDIM + ct) * LDIM + l0],     sacc[t][2]);
        atomicAdd(&dst[((size_t)(bg + 8) * CDIM + ct) * LDIM + l0 + 1], sacc[t][3]);
    }
}

__global__ void squash_out_kernel(const float* __restrict__ biases, float* __restrict__ out) {
    int idx = blockIdx.x * blockDim.x + threadIdx.x;   // (b*C + c)
    if (idx >= BATCH * CDIM) return;
    int c = idx % CDIM;
    float s[LDIM];
    float n2 = 0.0f;
#pragma unroll
    for (int l = 0; l < LDIM; ++l) {
        s[l] = g_s2[idx * LDIM + l] + biases[c * LDIM + l];
        n2 += s[l] * s[l];
    }
    float f = squash_factor(n2);
#pragma unroll
    for (int l = 0; l < LDIM; ++l) out[idx * LDIM + l] = f * s[l];
}

extern "C" void kernel_launch(void* const* d_in, const int* in_sizes, int n_in,
                              void* d_out, int out_size) {
    const float* inputs = (const float*)d_in[0];   // [128,4608,8]
    const float* W      = (const float*)d_in[1];   // [4608,8,160]
    const float* biases = (const float*)d_in[2];   // [10,16]
    float* out = (float*)d_out;                    // [128,10,16]

    cudaFuncSetAttribute(fused_pass<0>, cudaFuncAttributeMaxDynamicSharedMemorySize, SM_TOT);
    cudaFuncSetAttribute(fused_pass<1>, cudaFuncAttributeMaxDynamicSharedMemorySize, SM_TOT);
    cudaFuncSetAttribute(fused_pass<2>, cudaFuncAttributeMaxDynamicSharedMemorySize, SM_TOT);

    transpose_W_kernel<<<NCAP, CL>>>(W);           // also zeroes s0/s1/s2
    dim3 grid(BSPL, NSPL);                         // (4, 72) = 288 blocks
    fused_pass<0><<<grid, THR, SM_TOT>>>(inputs, biases);
    fused_pass<1><<<grid, THR, SM_TOT>>>(inputs, biases);
    fused_pass<2><<<grid, THR, SM_TOT>>>(inputs, biases);
    squash_out_kernel<<<(BATCH * CDIM + 255) / 256, 256>>>(biases, out);
}

// round 16
// speedup vs baseline: 1.1245x; 1.1245x over previous
#include <cuda_runtime.h>
#include <cuda_fp16.h>
#include <math.h>

#define BATCH 128
#define NCAP  4608
#define JDIM  8
#define CDIM  10
#define LDIM  16
#define CL    160
#define BSPL  4               // b-splits (32 b each)
#define NSPL  72              // n-splits
#define FN    (NCAP/NSPL)     // 64 n per block
#define THR   320
#define WST   2560            // bytes per W stage (160 rows * 16B)
#define EPAD  12              // floats per e-row (10 used + 2 zero pad)

typedef unsigned long long ull;

// smem byte offsets (dynamic smem)
#define SM_X   0                     // 64n*32b*8j fp16 = 32768
#define SM_W   32768                 // 8 stages * 2560 = 20480
#define SM_V   53248                 // 10c*32b*16l fp32 = 20480
#define SM_SE  73728                 // 2j * 32b * 12 fp32 = 3072
#define SM_TOT 76800

// Scratch (static device globals; no dynamic allocation allowed)
__device__ __align__(16) __half g_Wh[(size_t)NCAP * CL * JDIM];  // [n][cl][8j] fp16
__device__ __align__(16) float g_s0[BATCH * CDIM * LDIM];
__device__ __align__(16) float g_s1[BATCH * CDIM * LDIM];
__device__ __align__(16) float g_s2[BATCH * CDIM * LDIM];

// ---- packed f32x2 helpers ---------------------------------------------------
__device__ __forceinline__ ull pk2(float a, float b) {
    ull r; asm("mov.b64 %0,{%1,%2};" : "=l"(r) : "f"(a), "f"(b)); return r;
}
__device__ __forceinline__ ull fma2(ull a, ull b, ull c) {
    ull d; asm("fma.rn.f32x2 %0,%1,%2,%3;" : "=l"(d) : "l"(a), "l"(b), "l"(c)); return d;
}
__device__ __forceinline__ ull add2(ull a, ull b) {
    ull d; asm("add.rn.f32x2 %0,%1,%2;" : "=l"(d) : "l"(a), "l"(b)); return d;
}
__device__ __forceinline__ float lo2(ull a) {
    float f; asm("{ .reg .b32 h; mov.b64 {%0,h}, %1; }" : "=f"(f) : "l"(a)); return f;
}
__device__ __forceinline__ float hi2(ull a) {
    float f; asm("{ .reg .b32 l; mov.b64 {l,%0}, %1; }" : "=f"(f) : "l"(a)); return f;
}
__device__ __forceinline__ unsigned int cvt2h(float lo, float hi) {
    unsigned int h;
    asm("cvt.rn.f16x2.f32 %0, %1, %2;" : "=r"(h) : "f"(hi), "f"(lo));
    return h;
}
__device__ __forceinline__ float squash_factor(float n2) {
    return n2 / (1.0f + n2) / (sqrtf(n2) + 1e-7f);
}
// Fast exp on fma/alu pipes. |x| small, rel err ~4e-5.
__device__ __forceinline__ float fexp(float x) {
    float t = x * 1.4426950408889634f;
    float z = t + 12582912.0f;
    int   ki = __float_as_int(z);
    float k = z - 12582912.0f;
    float f = t - k;
    float p = 0.0096181291f;
    p = fmaf(p, f, 0.0555041087f);
    p = fmaf(p, f, 0.2402265070f);
    p = fmaf(p, f, 0.6931471806f);
    p = fmaf(p, f, 1.0f);
    return __int_as_float(__float_as_int(p) + (ki << 23));
}
__device__ __forceinline__ void cpasync16(unsigned int sdst, const void* gsrc) {
    asm volatile("cp.async.cg.shared.global [%0], [%1], 16;" :: "r"(sdst), "l"(gsrc) : "memory");
}
__device__ __forceinline__ void cpasync_commit() {
    asm volatile("cp.async.commit_group;" ::: "memory");
}
__device__ __forceinline__ void cpasync_wait4() {
    asm volatile("cp.async.wait_group 4;" ::: "memory");
}
__device__ __forceinline__ unsigned int smem_u32(const void* p) {
    return (unsigned int)__cvta_generic_to_shared(p);
}
__device__ __forceinline__ void ldsm_x2(unsigned int& r0, unsigned int& r1, unsigned int a) {
    asm volatile("ldmatrix.sync.aligned.m8n8.x2.shared.b16 {%0,%1}, [%2];"
                 : "=r"(r0), "=r"(r1) : "r"(a));
}
__device__ __forceinline__ void ldsm_x4(unsigned int& r0, unsigned int& r1,
                                        unsigned int& r2, unsigned int& r3, unsigned int a) {
    asm volatile("ldmatrix.sync.aligned.m8n8.x4.shared.b16 {%0,%1,%2,%3}, [%4];"
                 : "=r"(r0), "=r"(r1), "=r"(r2), "=r"(r3) : "r"(a));
}
__device__ __forceinline__ void mma_16n8k8(float* c, unsigned int a0, unsigned int a1,
                                           unsigned int b0) {
    asm volatile("mma.sync.aligned.m16n8k8.row.col.f32.f16.f16.f32 "
                 "{%0,%1,%2,%3}, {%4,%5}, {%6}, {%7,%7,%7,%7};"
                 : "=f"(c[0]), "=f"(c[1]), "=f"(c[2]), "=f"(c[3])
                 : "r"(a0), "r"(a1), "r"(b0), "f"(0.0f));
}

// ---------------------------------------------------------------------------
// W prep: W[n][j][cl] fp32 -> g_Wh[n][cl][8j] fp16; zero s buffers.
// ---------------------------------------------------------------------------
__global__ void transpose_W_kernel(const float* __restrict__ W) {
    int n = blockIdx.x;
    int cl = threadIdx.x;     // 0..159
    if (n < 128) {
        int z = n * CL + cl;
        g_s0[z] = 0.0f; g_s1[z] = 0.0f; g_s2[z] = 0.0f;
    }
    const float* Wn = W + (size_t)n * JDIM * CL;
    unsigned int h[4];
#pragma unroll
    for (int p = 0; p < 4; ++p)
        h[p] = cvt2h(Wn[(2 * p) * CL + cl], Wn[(2 * p + 1) * CL + cl]);
    *reinterpret_cast<uint4*>(g_Wh + ((size_t)n * CL + cl) * JDIM) =
        make_uint4(h[0], h[1], h[2], h[3]);
}

// ---------------------------------------------------------------------------
// Fused routing pass, G=2 n per barrier group. e-exchange rows padded to 12
// floats -> vectorized Sum(e) via LDS.128 + add2. All hot math in f32x2.
// Block: 32 b x 64 n. 320 thr / 10 warps; warp w: mt=w&1, cA=w>>1, cB=cA+5.
// MODE 0: s0 += u. MODE 1: v=squash(s0/C+bias); s1 += coef*u.
// MODE 2: v=squash(s0/C+bias)+squash(s1+bias);  s2 += coef*u.
// ---------------------------------------------------------------------------
template <int MODE>
__global__ __launch_bounds__(THR, 2) void fused_pass(const float* __restrict__ x,
                                                     const float* __restrict__ biases) {
    extern __shared__ __align__(16) char smem[];
    __half* sX = (__half*)(smem + SM_X);
    float*  sV = (float*)(smem + SM_V);
    float*  sE = (float*)(smem + SM_SE);     // [j][b][EPAD]

    const int tid  = threadIdx.x;
    const int lane = tid & 31;
    const int w    = tid >> 5;          // 0..9
    const int mt   = w & 1;
    const int cA   = w >> 1;            // 0..4
    const int cB   = cA + 5;
    const int Bb   = blockIdx.x * 32;
    const int nbeg = blockIdx.y * FN;

    // ---- prologue: stage x chunk (32 KB fp16) ----
    for (int k = tid; k < 32 * FN * 2; k += THR) {
        int b   = k >> 7;
        int rem = k & 127;
        int nl  = rem >> 1;
        int jh  = (rem & 1) * 4;
        float4 xv = *(const float4*)(x + ((size_t)(Bb + b) * NCAP + nbeg + nl) * JDIM + jh);
        *(uint2*)&sX[(nl * 32 + b) * JDIM + jh] =
            make_uint2(cvt2h(xv.x, xv.y), cvt2h(xv.z, xv.w));
    }
    // zero sE (pads must stay zero; cc 0..9 rewritten each group)
    if (MODE >= 1)
        for (int k = tid; k < 2 * 32 * EPAD; k += THR) sE[k] = 0.0f;
    // ---- prologue: v per (b,c) ----
    if (MODE >= 1) {
        int b = tid & 31, c = tid >> 5;
        const float4* s0p = (const float4*)(g_s0 + ((size_t)(Bb + b) * CDIM + c) * LDIM);
        const float4* bp  = (const float4*)(biases + c * LDIM);
        float v[16]; float n20 = 0.0f;
#pragma unroll
        for (int q = 0; q < 4; ++q) {
            float4 sv = s0p[q], bv = bp[q];
            v[q*4+0] = 0.1f*sv.x + bv.x; v[q*4+1] = 0.1f*sv.y + bv.y;
            v[q*4+2] = 0.1f*sv.z + bv.z; v[q*4+3] = 0.1f*sv.w + bv.w;
            n20 += v[q*4+0]*v[q*4+0] + v[q*4+1]*v[q*4+1]
                 + v[q*4+2]*v[q*4+2] + v[q*4+3]*v[q*4+3];
        }
        float f0 = squash_factor(n20);
        if (MODE == 1) {
#pragma unroll
            for (int l = 0; l < 16; ++l) v[l] *= f0;
        } else {
            const float4* s1p = (const float4*)(g_s1 + ((size_t)(Bb + b) * CDIM + c) * LDIM);
            float wv[16]; float n21 = 0.0f;
#pragma unroll
            for (int q = 0; q < 4; ++q) {
                float4 sv = s1p[q], bv = bp[q];
                wv[q*4+0] = sv.x + bv.x; wv[q*4+1] = sv.y + bv.y;
                wv[q*4+2] = sv.z + bv.z; wv[q*4+3] = sv.w + bv.w;
                n21 += wv[q*4+0]*wv[q*4+0] + wv[q*4+1]*wv[q*4+1]
                     + wv[q*4+2]*wv[q*4+2] + wv[q*4+3]*wv[q*4+3];
            }
            float f1 = squash_factor(n21);
#pragma unroll
            for (int l = 0; l < 16; ++l) v[l] = f0 * v[l] + f1 * wv[l];
        }
        float4* dv = (float4*)(sV + (c * 32 + b) * 16);
#pragma unroll
        for (int q = 0; q < 4; ++q)
            dv[q] = make_float4(v[q*4+0], v[q*4+1], v[q*4+2], v[q*4+3]);
    }
    __syncthreads();

    const int blq  = mt * 16 + (lane >> 2);
    const int lodd = (lane & 3) * 2;
    // packed v fragments: Vl2[t] = (v[l0], v[l0+1]) row blq; Vh2 row blq+8
    ull Vl2[4], Vh2[4];
    if (MODE >= 1) {
#pragma unroll
        for (int t = 0; t < 4; ++t) {
            int ct = (t < 2) ? cA : cB;
            int l0 = (t & 1) * 8 + lodd;
            Vl2[t] = pk2(sV[(ct * 32 + blq) * 16 + l0],
                         sV[(ct * 32 + blq) * 16 + l0 + 1]);
            Vh2[t] = pk2(sV[(ct * 32 + blq + 8) * 16 + l0],
                         sV[(ct * 32 + blq + 8) * 16 + l0 + 1]);
        }
    }

    // ---- W cp.async ring: 8 stages of 1 n each ----
    const unsigned int swb = smem_u32(smem + SM_W);
    auto fillW = [&](int stage, int i) {
        if (tid < CL && i < FN)
            cpasync16(swb + stage * WST + tid * 16,
                      g_Wh + ((size_t)(nbeg + i) * CL + tid) * JDIM);
    };
#pragma unroll
    for (int i = 0; i < 6; ++i) { fillW(i, i); cpasync_commit(); }

    const unsigned int aaddr0 = smem_u32(sX) + (mt * 16 + (lane & 15)) * JDIM * 2;
    const int clrow = ((lane < 16) ? cA * 16 + lane : cB * 16 + lane - 16);
    const unsigned int baddr0 = swb + clrow * 16;

    ull sacc2lo[4], sacc2hi[4];
#pragma unroll
    for (int t = 0; t < 4; ++t) { sacc2lo[t] = 0ull; sacc2hi[t] = 0ull; }

    for (int g = 0; g < FN / 2; ++g) {
        const int i0 = g * 2;
        cpasync_wait4();
        __syncthreads();                          // bar A: stages i0, i0+1 ready
        fillW((i0 + 6) & 7, i0 + 6); cpasync_commit();
        fillW((i0 + 7) & 7, i0 + 7); cpasync_commit();

        ull u2lo[2][4], u2hi[2][4];
#pragma unroll
        for (int j = 0; j < 2; ++j) {
            unsigned int a0, a1, bf0, bf1, bf2, bf3;
            ldsm_x2(a0, a1, aaddr0 + (i0 + j) * 512);
            ldsm_x4(bf0, bf1, bf2, bf3, baddr0 + ((i0 + j) & 7) * WST);
            float c4[4][4];
            mma_16n8k8(c4[0], a0, a1, bf0);
            mma_16n8k8(c4[1], a0, a1, bf1);
            mma_16n8k8(c4[2], a0, a1, bf2);
            mma_16n8k8(c4[3], a0, a1, bf3);
#pragma unroll
            for (int t = 0; t < 4; ++t) {
                u2lo[j][t] = pk2(c4[t][0], c4[t][1]);
                u2hi[j][t] = pk2(c4[t][2], c4[t][3]);
            }
        }

        if (MODE == 0) {
#pragma unroll
            for (int j = 0; j < 2; ++j)
#pragma unroll
                for (int t = 0; t < 4; ++t) {
                    sacc2lo[t] = add2(sacc2lo[t], u2lo[j][t]);
                    sacc2hi[t] = add2(sacc2hi[t], u2hi[j][t]);
                }
        } else {
#pragma unroll
            for (int j = 0; j < 2; ++j) {
                // packed dots: bd per (row, c)
                ull dla = fma2(u2lo[j][0], Vl2[0], fma2(u2lo[j][1], Vl2[1], 0ull));
                ull dha = fma2(u2hi[j][0], Vh2[0], fma2(u2hi[j][1], Vh2[1], 0ull));
                ull dlb = fma2(u2lo[j][2], Vl2[2], fma2(u2lo[j][3], Vl2[3], 0ull));
                ull dhb = fma2(u2hi[j][2], Vh2[2], fma2(u2hi[j][3], Vh2[3], 0ull));
                float bla = lo2(dla) + hi2(dla);
                float bha = lo2(dha) + hi2(dha);
                float blb = lo2(dlb) + hi2(dlb);
                float bhb = lo2(dhb) + hi2(dhb);
#pragma unroll
                for (int d = 1; d <= 2; d <<= 1) {
                    bla += __shfl_xor_sync(0xFFFFFFFFu, bla, d);
                    bha += __shfl_xor_sync(0xFFFFFFFFu, bha, d);
                    blb += __shfl_xor_sync(0xFFFFFFFFu, blb, d);
                    bhb += __shfl_xor_sync(0xFFFFFFFFu, bhb, d);
                }
                // distributed exchange: publish e = exp(bd) into [j][b][12]
                int sel = lane & 3;
                float bv = (sel == 0) ? bla : (sel == 1) ? bha : (sel == 2) ? blb : bhb;
                int bb = mt * 16 + (lane >> 2) + ((sel & 1) ? 8 : 0);
                int cc = (sel & 2) ? cB : cA;
                sE[(j * 32 + bb) * EPAD + cc] = fexp(bv);
            }
            __syncthreads();                      // bar B: all e-values ready
#pragma unroll
            for (int j = 0; j < 2; ++j) {
                const float* ejl = sE + (j * 32 + blq) * EPAD;
                const float* ejh = sE + (j * 32 + blq + 8) * EPAD;
                const ulonglong2* pl = (const ulonglong2*)ejl;
                const ulonglong2* ph = (const ulonglong2*)ejh;
                ulonglong2 l0 = pl[0], l1 = pl[1], l2 = pl[2];
                ulonglong2 h0 = ph[0], h1 = ph[1], h2 = ph[2];
                ull sl2 = add2(add2(add2(l0.x, l0.y), add2(l1.x, l1.y)), add2(l2.x, l2.y));
                ull sh2 = add2(add2(add2(h0.x, h0.y), add2(h1.x, h1.y)), add2(h2.x, h2.y));
                float Sl = lo2(sl2) + hi2(sl2);
                float Sh = lo2(sh2) + hi2(sh2);
                float il = __fdividef(1.0f, Sl);
                float ih = __fdividef(1.0f, Sh);
                float cla = ejl[cA] * il;
                float cha = ejh[cA] * ih;
                float clb = ejl[cB] * il;
                float chb = ejh[cB] * ih;
                ull cl_a = pk2(cla, cla), ch_a = pk2(cha, cha);
                ull cl_b = pk2(clb, clb), ch_b = pk2(chb, chb);
                sacc2lo[0] = fma2(u2lo[j][0], cl_a, sacc2lo[0]);
                sacc2lo[1] = fma2(u2lo[j][1], cl_a, sacc2lo[1]);
                sacc2lo[2] = fma2(u2lo[j][2], cl_b, sacc2lo[2]);
                sacc2lo[3] = fma2(u2lo[j][3], cl_b, sacc2lo[3]);
                sacc2hi[0] = fma2(u2hi[j][0], ch_a, sacc2hi[0]);
                sacc2hi[1] = fma2(u2hi[j][1], ch_a, sacc2hi[1]);
                sacc2hi[2] = fma2(u2hi[j][2], ch_b, sacc2hi[2]);
                sacc2hi[3] = fma2(u2hi[j][3], ch_b, sacc2hi[3]);
            }
        }
    }

    // flush partials
    float* dst = (MODE == 0) ? g_s0 : (MODE == 1) ? g_s1 : g_s2;
    const int bg = Bb + blq;
#pragma unroll
    for (int t = 0; t < 4; ++t) {
        int ct = (t < 2) ? cA : cB;
        int l0 = (t & 1) * 8 + lodd;
        atomicAdd(&dst[((size_t)bg * CDIM + ct) * LDIM + l0],     lo2(sacc2lo[t]));
        atomicAdd(&dst[((size_t)bg * CDIM + ct) * LDIM + l0 + 1], hi2(sacc2lo[t]));
        atomicAdd(&dst[((size_t)(bg + 8) * CDIM + ct) * LDIM + l0],     lo2(sacc2hi[t]));
        atomicAdd(&dst[((size_t)(bg + 8) * CDIM + ct) * LDIM + l0 + 1], hi2(sacc2hi[t]));
    }
}

__global__ void squash_out_kernel(const float* __restrict__ biases, float* __restrict__ out) {
    int idx = blockIdx.x * blockDim.x + threadIdx.x;   // (b*C + c)
    if (idx >= BATCH * CDIM) return;
    int c = idx % CDIM;
    float s[LDIM];
    float n2 = 0.0f;
#pragma unroll
    for (int l = 0; l < LDIM; ++l) {
        s[l] = g_s2[idx * LDIM + l] + biases[c * LDIM + l];
        n2 += s[l] * s[l];
    }
    float f = squash_factor(n2);
#pragma unroll
    for (int l = 0; l < LDIM; ++l) out[idx * LDIM + l] = f * s[l];
}

extern "C" void kernel_launch(void* const* d_in, const int* in_sizes, int n_in,
                              void* d_out, int out_size) {
    const float* inputs = (const float*)d_in[0];   // [128,4608,8]
    const float* W      = (const float*)d_in[1];   // [4608,8,160]
    const float* biases = (const float*)d_in[2];   // [10,16]
    float* out = (float*)d_out;                    // [128,10,16]

    cudaFuncSetAttribute(fused_pass<0>, cudaFuncAttributeMaxDynamicSharedMemorySize, SM_TOT);
    cudaFuncSetAttribute(fused_pass<1>, cudaFuncAttributeMaxDynamicSharedMemorySize, SM_TOT);
    cudaFuncSetAttribute(fused_pass<2>, cudaFuncAttributeMaxDynamicSharedMemorySize, SM_TOT);

    transpose_W_kernel<<<NCAP, CL>>>(W);           // also zeroes s0/s1/s2
    dim3 grid(BSPL, NSPL);                         // (4, 72) = 288 blocks
    fused_pass<0><<<grid, THR, SM_TOT>>>(inputs, biases);
    fused_pass<1><<<grid, THR, SM_TOT>>>(inputs, biases);
    fused_pass<2><<<grid, THR, SM_TOT>>>(inputs, biases);
    squash_out_kernel<<<(BATCH * CDIM + 255) / 256, 256>>>(biases, out);
}